// round 15
// baseline (speedup 1.0000x reference)
#include <cuda_runtime.h>

#define N_STFT 1025
#define NF     1024          // iterated freqs (fb rows 0 and 1024 are exactly zero)
#define NMEL   128
#define NTIME  1024
#define NBT    4096
#define R      8             // rows per CTA
#define TPR    64            // threads per row; thread owns f in [16t, 16t+16)
#define NTHR   512
#define NCTAS  (NBT / R)     // 512
#define NITER  20
#define NPAIR  8             // f-pairs per thread

#define LRc  0.3f
#define MOMc 0.9f
#define INVc (2.0f / 4096.0f)

// ---- smem layout (float units) ----
#define OFF_SPEC 0                 // [R][512] staging (entry/exit only, 2 passes)
#define OFF_W4   4096              // [512] float4: (w0(f0),w0(f1),w1(f0),w1(f1))
#define OFF_DIFF 6144              // [R][132] (int tmp for m0 during setup: 1056 >= 1024)
#define DIFF_STRIDE 132
#define OFF_MEL  7200              // [R][128]
#define OFF_A0   8224              // [R][128] segment partials S0
#define OFF_A1   9248              // [R][128] segment partials S1
#define OFF_B0   10272             // [R][64] continuation partials S0
#define OFF_B1   10784             // [R][64] continuation partials S1
#define OFF_BT0  11296             // [128] int  first continuation thread per mel
#define OFF_BT1  11424             // [128] int  second continuation thread per mel
#define OFF_M0S  11552             // [64] int   m0 at f=16t
#define OFF_BMS  11616             // [64] u32   boundary bitmaps (bits 1..15)
#define OFF_CB   11680             // [64] int   continuation flags
#define SMEM_FLOATS 11744          // 46976 B -> 2 CTA/SM (reg-limited anyway)

// Fused sweep: per f (ascending), optionally SGD-update spec (registers), and
// accumulate fresh spec into per-segment partials; plain-store flush at
// boundaries. A[m] overwritten by the unique segment-starter thread each sweep;
// a thread whose FIRST segment continues the previous thread's flushes to B[t].
// Max segment width ~22: a segment spans <= 3 threads (1 starter + <=2 conts).
template <bool UPD, bool ACC>
__device__ __forceinline__ void sweep(float* sm, int r, int t, bool cB,
                                      unsigned bm, int m0start,
                                      float2 (&spec)[NPAIR], float2 (&buf)[NPAIR])
{
    const float4* w4s = (const float4*)(sm + OFF_W4);
    const float* diffr = sm + OFF_DIFF + r * DIFF_STRIDE;
    float* A0 = sm + OFF_A0 + r * 128;
    float* A1 = sm + OFF_A1 + r * 128;
    float* B0 = sm + OFF_B0 + r * 64;
    float* B1 = sm + OFF_B1 + r * 64;

    int cur = m0start;
    float d0 = 0.f, d1 = 0.f, acc0 = 0.f, acc1 = 0.f;
    bool first = true;
    if (UPD) { d0 = diffr[cur]; d1 = diffr[cur + 1]; }

    #pragma unroll
    for (int p = 0; p < NPAIR; ++p) {
        float4 w = w4s[p * TPR + t];

        // ---- element 0 (f = 16t + 2p); bit 0 never set (cB covers it) ----
        if ((bm >> (2 * p)) & 1u) {
            if (ACC) {
                bool toB = first & cB;
                float* q0 = toB ? (B0 + t) : (A0 + cur);
                float* q1 = toB ? (B1 + t) : (A1 + cur);
                *q0 = acc0; *q1 = acc1;
                acc0 = 0.f; acc1 = 0.f;
            }
            first = false; cur++;
            if (UPD) { d0 = diffr[cur]; d1 = diffr[cur + 1]; }
        }
        if (UPD) {
            float g = d0 * w.x + d1 * w.z;
            buf[p].x = MOMc * buf[p].x - INVc * g;
            spec[p].x = fmaxf(spec[p].x - LRc * buf[p].x, 0.f);
        }
        if (ACC) { acc0 = fmaf(spec[p].x, w.x, acc0); acc1 = fmaf(spec[p].x, w.z, acc1); }

        // ---- element 1 (f = 16t + 2p + 1) ----
        if ((bm >> (2 * p + 1)) & 1u) {
            if (ACC) {
                bool toB = first & cB;
                float* q0 = toB ? (B0 + t) : (A0 + cur);
                float* q1 = toB ? (B1 + t) : (A1 + cur);
                *q0 = acc0; *q1 = acc1;
                acc0 = 0.f; acc1 = 0.f;
            }
            first = false; cur++;
            if (UPD) { d0 = diffr[cur]; d1 = diffr[cur + 1]; }
        }
        if (UPD) {
            float g = d0 * w.y + d1 * w.w;
            buf[p].y = MOMc * buf[p].y - INVc * g;
            spec[p].y = fmaxf(spec[p].y - LRc * buf[p].y, 0.f);
        }
        if (ACC) { acc0 = fmaf(spec[p].y, w.y, acc0); acc1 = fmaf(spec[p].y, w.w, acc1); }
    }
    if (ACC) {
        bool toB = first & cB;
        float* q0 = toB ? (B0 + t) : (A0 + cur);
        float* q1 = toB ? (B1 + t) : (A1 + cur);
        *q0 = acc0; *q1 = acc1;
    }
}

// diff[r][m] = mel - S0(m) - S1(m-1), summing A plus up to two B contributions
// per mel (fixed order -> deterministic). No re-zeroing: every read slot is
// rewritten by its owner every sweep (A0[127] one-time zeroed at setup).
__device__ __forceinline__ void combine(float* sm, int tid)
{
    const int* bt0a = (const int*)(sm + OFF_BT0);
    const int* bt1a = (const int*)(sm + OFF_BT1);
    #pragma unroll
    for (int k = 0; k < 2; ++k) {
        int idx = tid + k * NTHR;          // 0..1023
        int m  = idx & 127;
        int rr = idx >> 7;
        float a0 = sm[OFF_A0 + rr * 128 + m];
        int p0 = bt0a[m], p1 = bt1a[m];
        if (p0 >= 0) a0 += sm[OFF_B0 + rr * 64 + p0];
        if (p1 >= 0) a0 += sm[OFF_B0 + rr * 64 + p1];
        float v = sm[OFF_MEL + rr * 128 + m] - a0;
        if (m > 0) {
            float a1 = sm[OFF_A1 + rr * 128 + (m - 1)];
            int q0 = bt0a[m - 1], q1 = bt1a[m - 1];
            if (q0 >= 0) a1 += sm[OFF_B1 + rr * 64 + q0];
            if (q1 >= 0) a1 += sm[OFF_B1 + rr * 64 + q1];
            v -= a1;
        }
        sm[OFF_DIFF + rr * DIFF_STRIDE + m] = v;
    }
}

__global__ void __launch_bounds__(NTHR, 2)
imel_kernel(const float* __restrict__ mel_in,     // (B, M, T)
            const float* __restrict__ spec_init,  // (B, T, F)
            const float* __restrict__ fb,         // (F, M)
            float* __restrict__ out)              // (B, F, T)
{
    extern __shared__ float sm[];
    const int tid  = threadIdx.x;
    const int r    = tid >> 6;     // row in CTA (0..7)
    const int t    = tid & 63;     // thread within row
    const int row0 = blockIdx.x * R;
    const int b    = row0 / NTIME;
    const int t0   = row0 & (NTIME - 1);

    int* tmpm0 = (int*)(sm + OFF_DIFF);   // reuse diff region during setup
    int* m0s   = (int*)(sm + OFF_M0S);
    unsigned* bms = (unsigned*)(sm + OFF_BMS);
    int* cont  = (int*)(sm + OFF_CB);
    int* bt0a  = (int*)(sm + OFF_BT0);
    int* bt1a  = (int*)(sm + OFF_BT1);

    // ---- weights + m0 per f (<=2 nonzeros per triangular fb row) ----
    {                                      // slot = p*64 + tt == tid (512 slots)
        int p = tid >> 6, tt = tid & 63;
        int f0 = tt * 16 + p * 2;
        float w0v[2], w1v[2];
        #pragma unroll
        for (int e = 0; e < 2; ++e) {
            const float* fr = fb + (size_t)(f0 + e) * NMEL;
            int fm = 0;
            while (fm < NMEL && fr[fm] <= 0.0f) fm++;
            int m0 = (fm >= NMEL) ? 0 : (fm > 126 ? 126 : fm);  // zero row -> m0=0, w=0
            w0v[e] = fr[m0];
            w1v[e] = fr[m0 + 1];
            tmpm0[f0 + e] = m0;
        }
        ((float4*)(sm + OFF_W4))[tid] = make_float4(w0v[0], w0v[1], w1v[0], w1v[1]);
    }
    // ---- mel transpose ----
    for (int idx = tid; idx < R * NMEL; idx += NTHR) {
        int m = idx >> 3, rr = idx & (R - 1);
        sm[OFF_MEL + rr * 128 + m] =
            mel_in[((size_t)b * NMEL + m) * NTIME + t0 + rr];
    }
    // ---- one-time zero: A0 col 127 has no segment; clear both A arrays once ----
    for (int idx = tid; idx < R * 128; idx += NTHR) {
        sm[OFF_A0 + idx] = 0.f;
        sm[OFF_A1 + idx] = 0.f;
    }
    if (tid < NMEL) { bt0a[tid] = -1; bt1a[tid] = -1; }
    __syncthreads();
    // ---- boundary bitmaps (m0 steps by exactly +1 at each boundary) ----
    if (tid < TPR) {
        unsigned bmv = 0u;
        int prev = tmpm0[tid * 16];
        m0s[tid] = prev;
        for (int i = 1; i < 16; ++i) {
            int cm = tmpm0[tid * 16 + i];
            if (cm != prev) bmv |= (1u << i);
            prev = cm;
        }
        bms[tid] = bmv;
        cont[tid] = (tid > 0 && tmpm0[tid * 16] == tmpm0[tid * 16 - 1]) ? 1 : 0;
    }
    __syncthreads();
    // ---- continuation thread tables: up to TWO continuation threads per mel ----
    if (tid == 0) {
        for (int tt = 1; tt < TPR; ++tt) {
            if (cont[tt]) {
                int m = tmpm0[tt * 16];
                if (bt0a[m] < 0) bt0a[m] = tt;
                else             bt1a[m] = tt;
            }
        }
    }
    __syncthreads();

    const unsigned bm = bms[t];
    const int m0start = m0s[t];
    const bool cB     = cont[t] != 0;

    // ---- load spec into registers via staging, two half passes ----
    float2 spec[NPAIR], buf[NPAIR];
    #pragma unroll
    for (int p = 0; p < NPAIR; ++p) buf[p] = make_float2(0.f, 0.f);
    #pragma unroll
    for (int h = 0; h < 2; ++h) {
        for (int idx = tid; idx < R * 512; idx += NTHR) {
            int rr = idx >> 9, f = idx & 511;
            sm[OFF_SPEC + idx] = spec_init[(size_t)(row0 + rr) * N_STFT + h * 512 + f];
        }
        __syncthreads();
        if ((t >> 5) == h) {
            int tb = t & 31;
            #pragma unroll
            for (int p = 0; p < NPAIR; ++p)
                spec[p] = *(const float2*)&sm[OFF_SPEC + r * 512 + tb * 16 + 2 * p];
        }
        __syncthreads();
    }

    // sweep0: accumulate partials from initial spec (no update)
    sweep<false, true>(sm, r, t, cB, bm, m0start, spec, buf);
    __syncthreads();
    combine(sm, tid);
    __syncthreads();

    for (int it = 1; it < NITER; ++it) {
        sweep<true, true>(sm, r, t, cB, bm, m0start, spec, buf);
        __syncthreads();
        combine(sm, tid);
        __syncthreads();
    }
    // last iteration: update only, no accumulate/flush
    sweep<true, false>(sm, r, t, cB, bm, m0start, spec, buf);

    // ---- output via staging, two half passes: out[b][f][t0..t0+7] ----
    #pragma unroll
    for (int h = 0; h < 2; ++h) {
        __syncthreads();
        if ((t >> 5) == h) {
            int tb = t & 31;
            #pragma unroll
            for (int p = 0; p < NPAIR; ++p)
                *(float2*)&sm[OFF_SPEC + r * 512 + tb * 16 + 2 * p] = spec[p];
        }
        __syncthreads();
        {
            int f = h * 512 + tid;
            float v[R];
            #pragma unroll
            for (int j = 0; j < R; ++j) v[j] = sm[OFF_SPEC + j * 512 + tid];
            float* op = out + ((size_t)b * N_STFT + f) * NTIME + t0;
            #pragma unroll
            for (int j = 0; j < R; j += 4)
                *(float4*)&op[j] = make_float4(v[j], v[j + 1], v[j + 2], v[j + 3]);
        }
    }
    // f = 1024 is static (fb row exactly zero)
    if (tid < R) {
        out[((size_t)b * N_STFT + 1024) * NTIME + t0 + tid] =
            spec_init[(size_t)(row0 + tid) * N_STFT + 1024];
    }
}

extern "C" void kernel_launch(void* const* d_in, const int* in_sizes, int n_in,
                              void* d_out, int out_size)
{
    const float* mel_in    = (const float*)d_in[0];  // (4,128,1024)
    const float* spec_init = (const float*)d_in[1];  // (4,1024,1025)
    const float* fb        = (const float*)d_in[2];  // (1025,128)
    float* out             = (float*)d_out;          // (4,1025,1024)

    size_t smem = SMEM_FLOATS * sizeof(float);
    cudaFuncSetAttribute(imel_kernel, cudaFuncAttributeMaxDynamicSharedMemorySize, (int)smem);
    imel_kernel<<<NCTAS, NTHR, smem>>>(mel_in, spec_init, fb, out);
}

// round 16
// speedup vs baseline: 1.2490x; 1.2490x over previous
#include <cuda_runtime.h>

#define N_STFT 1025
#define NF     1024          // iterated freqs (fb rows 0 and 1024 are exactly zero)
#define NMEL   128
#define NTIME  1024
#define NBT    4096
#define R      16            // rows per CTA
#define TPR    16            // threads per row; thread owns f in [64t, 64t+64)
#define NTHR   256
#define NCTAS  (NBT / R)     // 256 -> single wave at 2 CTA/SM
#define NITER  20
#define NPAIR  32            // f-pairs per thread

#define LRc  0.3f
#define MOMc 0.9f
#define INVc (2.0f / 4096.0f)

// ---- smem layout (float units) ----
#define OFF_SPEC 0                 // [R][512] float2 perm slots (slot = p*16+t)
#define OFF_W4   16384             // [512] float4: (w0(f0),w0(f1),w1(f0),w1(f1))
#define OFF_DIFF 18432             // [R][132] (int tmp for m0 during setup)
#define DIFF_STRIDE 132
#define OFF_MEL  20544             // [R][128]
#define OFF_A0   22592             // [R][128] segment partials S0
#define OFF_A1   24640             // [R][128] segment partials S1
#define OFF_B0   26688             // [R][16] continuation partials S0
#define OFF_B1   26944             // [R][16] continuation partials S1
#define OFF_BT   27200             // [128] int  continuation thread per mel (<=1)
#define OFF_M0S  27328             // [16] int   m0 at f=64t
#define OFF_BM   27352             // [16] u64   boundary bitmaps (8B aligned)
#define OFF_CB   27384             // [16] int   continuation flags
#define SMEM_FLOATS 27400          // 109600 B -> 2 CTA/SM

// Fused sweep: per f (ascending), optionally SGD-update spec, and accumulate
// the fresh spec into per-segment partials; plain-store flush at boundaries.
// A[m] written by the unique closing thread (non-first flush); a thread whose
// FIRST segment continues the previous thread's flushes to B[t] instead.
// Max segment width ~22 < 64 -> a segment spans <= 2 threads (<=1 continuation).
template <bool UPD, bool ACC>
__device__ __forceinline__ void sweep(float* sm, int r, int t, bool cB,
                                      unsigned long long bm, int m0start,
                                      float2 (&buf)[NPAIR])
{
    float2* sp2 = (float2*)(sm + OFF_SPEC) + r * 512;
    const float4* w4s = (const float4*)(sm + OFF_W4);
    const float* diffr = sm + OFF_DIFF + r * DIFF_STRIDE;
    float* A0 = sm + OFF_A0 + r * 128;
    float* A1 = sm + OFF_A1 + r * 128;
    float* B0 = sm + OFF_B0 + r * 16;
    float* B1 = sm + OFF_B1 + r * 16;

    int cur = m0start;
    float d0 = 0.f, d1 = 0.f, acc0 = 0.f, acc1 = 0.f;
    bool first = true;
    if (UPD) { d0 = diffr[cur]; d1 = diffr[cur + 1]; }

    #pragma unroll
    for (int p = 0; p < NPAIR; ++p) {
        const int slot = p * TPR + t;
        float2 s = sp2[slot];
        float4 w = w4s[slot];

        // ---- element 0 (f = 64t + 2p); bit 0 never set (cB covers it) ----
        if ((bm >> (2 * p)) & 1ull) {
            if (ACC) {
                bool toB = first & cB;
                float* q0 = toB ? (B0 + t) : (A0 + cur);
                float* q1 = toB ? (B1 + t) : (A1 + cur);
                *q0 = acc0; *q1 = acc1;
                acc0 = 0.f; acc1 = 0.f;
            }
            first = false; cur++;
            if (UPD) { d0 = diffr[cur]; d1 = diffr[cur + 1]; }
        }
        if (UPD) {
            float g = d0 * w.x + d1 * w.z;
            buf[p].x = MOMc * buf[p].x - INVc * g;
            s.x = fmaxf(s.x - LRc * buf[p].x, 0.f);
        }
        if (ACC) { acc0 = fmaf(s.x, w.x, acc0); acc1 = fmaf(s.x, w.z, acc1); }

        // ---- element 1 (f = 64t + 2p + 1) ----
        if ((bm >> (2 * p + 1)) & 1ull) {
            if (ACC) {
                bool toB = first & cB;
                float* q0 = toB ? (B0 + t) : (A0 + cur);
                float* q1 = toB ? (B1 + t) : (A1 + cur);
                *q0 = acc0; *q1 = acc1;
                acc0 = 0.f; acc1 = 0.f;
            }
            first = false; cur++;
            if (UPD) { d0 = diffr[cur]; d1 = diffr[cur + 1]; }
        }
        if (UPD) {
            float g = d0 * w.y + d1 * w.w;
            buf[p].y = MOMc * buf[p].y - INVc * g;
            s.y = fmaxf(s.y - LRc * buf[p].y, 0.f);
        }
        if (ACC) { acc0 = fmaf(s.y, w.y, acc0); acc1 = fmaf(s.y, w.w, acc1); }

        if (UPD) sp2[slot] = s;
    }
    if (ACC) {
        bool toB = first & cB;
        float* q0 = toB ? (B0 + t) : (A0 + cur);
        float* q1 = toB ? (B1 + t) : (A1 + cur);
        *q0 = acc0; *q1 = acc1;
    }
}

// diff[r][m] = mel - S0(m) - S1(m-1); A plus at most one B contribution per mel
// (fixed order -> deterministic). A slots rewritten by owners every sweep;
// A0/A1[127] zeroed once at setup and never written.
__device__ __forceinline__ void combine(float* sm, int tid)
{
    const int* bthr = (const int*)(sm + OFF_BT);
    #pragma unroll
    for (int k = 0; k < 8; ++k) {
        int idx = tid + k * NTHR;          // 0..2047
        int m  = idx & 127;
        int rr = idx >> 7;
        float a0 = sm[OFF_A0 + rr * 128 + m];
        int bt = bthr[m];
        if (bt >= 0) a0 += sm[OFF_B0 + rr * 16 + bt];
        float v = sm[OFF_MEL + rr * 128 + m] - a0;
        if (m > 0) {
            float a1 = sm[OFF_A1 + rr * 128 + (m - 1)];
            int bt1 = bthr[m - 1];
            if (bt1 >= 0) a1 += sm[OFF_B1 + rr * 16 + bt1];
            v -= a1;
        }
        sm[OFF_DIFF + rr * DIFF_STRIDE + m] = v;
    }
}

__global__ void __launch_bounds__(NTHR, 2)
imel_kernel(const float* __restrict__ mel_in,     // (B, M, T)
            const float* __restrict__ spec_init,  // (B, T, F)
            const float* __restrict__ fb,         // (F, M)
            float* __restrict__ out)              // (B, F, T)
{
    extern __shared__ float sm[];
    const int tid  = threadIdx.x;
    const int r    = tid >> 4;     // row in CTA (0..15)
    const int t    = tid & 15;     // thread within row
    const int row0 = blockIdx.x * R;
    const int b    = row0 / NTIME;
    const int t0   = row0 & (NTIME - 1);

    int* tmpm0 = (int*)(sm + OFF_DIFF);   // reuse diff region during setup (2112 ints)
    int* m0s   = (int*)(sm + OFF_M0S);
    unsigned long long* bms = (unsigned long long*)(sm + OFF_BM);
    int* cont  = (int*)(sm + OFF_CB);
    int* bthr  = (int*)(sm + OFF_BT);

    // ---- spec into perm layout: slot(f) = ((f&63)>>1)*16 + (f>>6), elem f&1 ----
    for (int idx = tid; idx < R * NF; idx += NTHR) {
        int rr = idx >> 10, f = idx & 1023;
        int pos = (((f & 63) >> 1) * TPR + (f >> 6)) * 2 + (f & 1);
        sm[OFF_SPEC + rr * 1024 + pos] = spec_init[(size_t)(row0 + rr) * N_STFT + f];
    }
    // ---- mel transpose ----
    for (int idx = tid; idx < R * NMEL; idx += NTHR) {
        int m = idx >> 4, rr = idx & (R - 1);
        sm[OFF_MEL + rr * 128 + m] =
            mel_in[((size_t)b * NMEL + m) * NTIME + t0 + rr];
    }
    // ---- weights + m0 per f (<=2 nonzeros per triangular fb row) ----
    for (int q = tid; q < 512; q += NTHR) {
        int tt = q & 15, pp = q >> 4;
        int slot = pp * TPR + tt;
        int f0 = tt * 64 + pp * 2;
        float w0v[2], w1v[2];
        #pragma unroll
        for (int e = 0; e < 2; ++e) {
            const float* fr = fb + (size_t)(f0 + e) * NMEL;
            int fm = 0;
            while (fm < NMEL && fr[fm] <= 0.0f) fm++;
            int m0 = (fm >= NMEL) ? 0 : (fm > 126 ? 126 : fm);  // zero row -> m0=0, w=0
            w0v[e] = fr[m0];
            w1v[e] = fr[m0 + 1];
            tmpm0[f0 + e] = m0;
        }
        ((float4*)(sm + OFF_W4))[slot] = make_float4(w0v[0], w0v[1], w1v[0], w1v[1]);
    }
    // ---- one-time zero of A arrays (slots for mel 127 are never rewritten) ----
    for (int idx = tid; idx < R * 128; idx += NTHR) {
        sm[OFF_A0 + idx] = 0.f;
        sm[OFF_A1 + idx] = 0.f;
    }
    if (tid < NMEL) bthr[tid] = -1;
    __syncthreads();
    // ---- boundary bitmaps (m0 steps by exactly +1 at each boundary) ----
    if (tid < TPR) {
        unsigned long long bmv = 0ull;
        int prev = tmpm0[tid * 64];
        m0s[tid] = prev;
        for (int i = 1; i < 64; ++i) {
            int cm = tmpm0[tid * 64 + i];
            if (cm != prev) bmv |= (1ull << i);
            prev = cm;
        }
        bms[tid] = bmv;
        cont[tid] = (tid > 0 && tmpm0[tid * 64] == tmpm0[tid * 64 - 1]) ? 1 : 0;
    }
    __syncthreads();
    if (tid < TPR && cont[tid]) bthr[tmpm0[tid * 64]] = tid;
    __syncthreads();

    const unsigned long long bm = bms[t];
    const int m0start = m0s[t];
    const bool cB     = cont[t] != 0;

    float2 buf[NPAIR];
    #pragma unroll
    for (int p = 0; p < NPAIR; ++p) buf[p] = make_float2(0.f, 0.f);

    // sweep0: accumulate partials from initial spec (no update)
    sweep<false, true>(sm, r, t, cB, bm, m0start, buf);
    __syncthreads();
    combine(sm, tid);
    __syncthreads();

    for (int it = 1; it < NITER; ++it) {
        sweep<true, true>(sm, r, t, cB, bm, m0start, buf);
        __syncthreads();
        combine(sm, tid);
        __syncthreads();
    }
    // last iteration: update only, no accumulate/flush
    sweep<true, false>(sm, r, t, cB, bm, m0start, buf);
    __syncthreads();

    // ---- output: out[b][f][t0..t0+15]; f=1024 is static (fb row zero) ----
    for (int f = tid; f < N_STFT; f += NTHR) {
        float v[R];
        if (f < NF) {
            int pos = (((f & 63) >> 1) * TPR + (f >> 6)) * 2 + (f & 1);
            #pragma unroll
            for (int j = 0; j < R; ++j) v[j] = sm[OFF_SPEC + j * 1024 + pos];
        } else {
            #pragma unroll
            for (int j = 0; j < R; ++j)
                v[j] = spec_init[(size_t)(row0 + j) * N_STFT + 1024];
        }
        float* op = out + ((size_t)b * N_STFT + f) * NTIME + t0;
        #pragma unroll
        for (int j = 0; j < R; j += 4)
            *(float4*)&op[j] = make_float4(v[j], v[j + 1], v[j + 2], v[j + 3]);
    }
}

extern "C" void kernel_launch(void* const* d_in, const int* in_sizes, int n_in,
                              void* d_out, int out_size)
{
    const float* mel_in    = (const float*)d_in[0];  // (4,128,1024)
    const float* spec_init = (const float*)d_in[1];  // (4,1024,1025)
    const float* fb        = (const float*)d_in[2];  // (1025,128)
    float* out             = (float*)d_out;          // (4,1025,1024)

    size_t smem = SMEM_FLOATS * sizeof(float);
    cudaFuncSetAttribute(imel_kernel, cudaFuncAttributeMaxDynamicSharedMemorySize, (int)smem);
    imel_kernel<<<NCTAS, NTHR, smem>>>(mel_in, spec_init, fb, out);
}